// round 6
// baseline (speedup 1.0000x reference)
#include <cuda_runtime.h>

// out[b, o] = max_i min(x[b, i], W[i, o])   (fuzzy max-min composition)
// x: [1024, 512] f32, W: [512, 512] f32, out: [1024, 512] f32.
//
// R6: threshold bitmask probing, exact fp32.
//   For threshold θ: out[b,o] >= θ  <=>  X_b(θ) & W_o(θ) != 0, where the
//   masks are 512-bit "value >= θ" indicators. Moreover the argmax index
//   lies inside ANY nonempty intersection (both its values >= out >= θ).
//   So: probe a coarsening θ ladder, stop at the FIRST nonempty
//   intersection, and take the exact max-min over its few set bits.
//   Uniform inputs: ~1.5 probes and ~2 set bits per (b,o) pair.
//   Dense 512-iter fallback preserves correctness for arbitrary inputs.

#define B_DIM 1024
#define IN_F  512
#define OUT_F 512
#define NL    7      // threshold levels, fine -> coarse
#define NW    16     // 512 bits = 16 x u32 words

// theta_t = 1 - sqrt(c_t / 512), c = {1,2,4,8,16,32,64}
__device__ __constant__ float THETA[NL] = {
    0.95580584f, 0.93750000f, 0.91161165f, 0.87500000f,
    0.82322330f, 0.75000000f, 0.64644661f
};

// W column masks: g_wm[level][o][word]  (7*512*16 u32 = 224 KB, L2-resident)
__device__ unsigned g_wm[NL * OUT_F * NW];

// ---------------- prepass: build W column masks ----------------
// 64 blocks x 256 threads; warp handles one column o.
__global__ __launch_bounds__(256)
void build_wmasks(const float* __restrict__ w)
{
    const int warp = threadIdx.x >> 5;
    const int lane = threadIdx.x & 31;
    const int o    = blockIdx.x * 8 + warp;

#pragma unroll
    for (int ch = 0; ch < NW; ch++) {
        float v = w[(ch * 32 + lane) * OUT_F + o];
#pragma unroll
        for (int t = 0; t < NL; t++) {
            unsigned m = __ballot_sync(0xFFFFFFFFu, v >= THETA[t]);
            if (lane == 0) g_wm[(t * OUT_F + o) * NW + ch] = m;
        }
    }
}

// ---------------- main: probe + exact refine ----------------
// Block per batch row b, thread per output o.
__global__ __launch_bounds__(512)
void maxmin_probe(const float* __restrict__ x,
                  const float* __restrict__ w,
                  float* __restrict__ out)
{
    __shared__ float    xs[IN_F];
    __shared__ unsigned xmask[NL][NW];

    const int b = blockIdx.x;
    const int t = threadIdx.x;        // == o
    const int wp = t >> 5, ln = t & 31;

    float v = x[b * IN_F + t];
    xs[t] = v;
    // build this row's masks in-block: warp wp owns word wp
#pragma unroll
    for (int lv = 0; lv < NL; lv++) {
        unsigned m = __ballot_sync(0xFFFFFFFFu, v >= THETA[lv]);
        if (ln == 0) xmask[lv][wp] = m;
    }
    __syncthreads();

    const int o = t;
    float best = 0.0f;                // inputs >= 0: 0 is max-identity
    bool found = false;

#pragma unroll 1
    for (int lv = 0; lv < NL; lv++) {
        if (found) break;
        const uint4* wpm = (const uint4*)&g_wm[(lv * OUT_F + o) * NW];
        uint4 w0 = wpm[0], w1 = wpm[1], w2 = wpm[2], w3 = wpm[3];
        const unsigned* xm = xmask[lv];   // warp-uniform broadcast reads

        unsigned A[NW];
        A[0]=w0.x&xm[0];  A[1]=w0.y&xm[1];  A[2]=w0.z&xm[2];  A[3]=w0.w&xm[3];
        A[4]=w1.x&xm[4];  A[5]=w1.y&xm[5];  A[6]=w1.z&xm[6];  A[7]=w1.w&xm[7];
        A[8]=w2.x&xm[8];  A[9]=w2.y&xm[9];  A[10]=w2.z&xm[10];A[11]=w2.w&xm[11];
        A[12]=w3.x&xm[12];A[13]=w3.y&xm[13];A[14]=w3.z&xm[14];A[15]=w3.w&xm[15];

        unsigned any = 0;
#pragma unroll
        for (int k = 0; k < NW; k++) any |= A[k];

        if (any) {
            found = true;
#pragma unroll 1
            for (int wd = 0; wd < NW; wd++) {
                unsigned u = A[wd];
                while (u) {
                    int bit = __ffs(u) - 1;
                    u &= u - 1;
                    int i = wd * 32 + bit;
                    best = fmaxf(best, fminf(xs[i], w[i * OUT_F + o]));
                }
            }
        }
    }

    if (!found) {   // arbitrary-input fallback (never taken for uniform data)
#pragma unroll 1
        for (int i = 0; i < IN_F; i++)
            best = fmaxf(best, fminf(xs[i], w[i * OUT_F + o]));
    }

    out[b * OUT_F + o] = best;
}

extern "C" void kernel_launch(void* const* d_in, const int* in_sizes, int n_in,
                              void* d_out, int out_size)
{
    const float* x = (const float*)d_in[0];   // [1024, 512]
    const float* w = (const float*)d_in[1];   // [512, 512]
    float* out = (float*)d_out;               // [1024, 512]

    build_wmasks<<<OUT_F / 8, 256>>>(w);
    maxmin_probe<<<B_DIM, 512>>>(x, w, out);
}

// round 7
// speedup vs baseline: 2.1598x; 2.1598x over previous
#include <cuda_runtime.h>
#include <cuda_fp16.h>

// out[b, o] = max_i min(x[b, i], W[i, o])   (fuzzy max-min composition)
// x: [1024, 512] f32, W: [512, 512] f32, out: [1024, 512] f32.
//
// R7: dense fp16 HMNMX2, re-tiled against the two measured co-limiters:
//  - 4m x 4n per thread: per k = 1 LDS.128 + 1 LDS.64 + 16 HMNMX2
//    (crossbar 768B/warp-k vs ALU 8cyc/warp-k -> ALU-bound, was co-saturated)
//  - 1024 single-warp CTAs (32m x 16n tile): 1024/148 = 6.92 -> ~1% wave
//    quantization (was 15% at 512 CTAs), __syncwarp instead of __syncthreads.
// Prepass (1 launch) converts x -> transposed dup-half2, w -> packed half2.

#define B_DIM 1024
#define IN_F  512
#define OUT_F 512

// scratch: x duplicated-half2, transposed [k][m]  (2 MB)
__device__ __align__(16) unsigned g_xd[IN_F * B_DIM];
// scratch: w packed-half2 [k][n/2]  (512 KB)
__device__ __align__(16) unsigned g_wh[IN_F * OUT_F / 2];

// ================= merged prepass =================
#define PREP_THREADS 256
#define XT_STRIDE 68

__global__ __launch_bounds__(PREP_THREADS)
void prep_kernel(const float* __restrict__ x, const float* __restrict__ w)
{
    const int t = threadIdx.x;

    if (blockIdx.x < 128) {
        // ---- x: [m][k] f32 -> [k][m] dup-half2, 64x64 tiles ----
        __shared__ unsigned t64[64][XT_STRIDE];
        const int bk = (blockIdx.x & 7) * 64;
        const int bm = (blockIdx.x >> 3) * 64;
#pragma unroll
        for (int it = 0; it < 4; it++) {
            int v = t + it * PREP_THREADS;       // 0..1023
            int r = v >> 4;                      // m row 0..63
            int c = v & 15;                      // k float4-chunk
            float4 f = *(const float4*)(x + (bm + r) * IN_F + bk + c * 4);
            __half2 h0 = __float2half2_rn(f.x);
            __half2 h1 = __float2half2_rn(f.y);
            __half2 h2 = __float2half2_rn(f.z);
            __half2 h3 = __float2half2_rn(f.w);
            t64[c * 4 + 0][r] = *(unsigned*)&h0;
            t64[c * 4 + 1][r] = *(unsigned*)&h1;
            t64[c * 4 + 2][r] = *(unsigned*)&h2;
            t64[c * 4 + 3][r] = *(unsigned*)&h3;
        }
        __syncthreads();
#pragma unroll
        for (int it = 0; it < 4; it++) {
            int v = t + it * PREP_THREADS;
            int kr = v >> 4;
            int mc = (v & 15) * 4;
            uint4 u = *(const uint4*)&t64[kr][mc];
            *(uint4*)&g_xd[(bk + kr) * B_DIM + bm + mc] = u;
        }
    } else {
        // ---- w: f32 pairs -> packed half2 ----
        const int wid = blockIdx.x - 128;
        const int f4base = wid * 512 + t * 2;
        float4 a = ((const float4*)w)[f4base];
        float4 b = ((const float4*)w)[f4base + 1];
        __half2 h0 = __floats2half2_rn(a.x, a.y);
        __half2 h1 = __floats2half2_rn(a.z, a.w);
        __half2 h2 = __floats2half2_rn(b.x, b.y);
        __half2 h3 = __floats2half2_rn(b.z, b.w);
        ((uint4*)g_wh)[wid * 256 + t] = make_uint4(
            *(unsigned*)&h0, *(unsigned*)&h1, *(unsigned*)&h2, *(unsigned*)&h3);
    }
}

// ================= main kernel: single-warp CTAs =================
#define BM 32
#define BN 16
#define BK 64
#define NKT (IN_F / BK)   // 8

__device__ __forceinline__ void issue_stage(int t, int bm, int bn_h, int kt,
                                            unsigned (*xs)[BM], unsigned (*ws)[BN / 2])
{
#pragma unroll
    for (int it = 0; it < 16; it++) {           // 64x32 uints = 512 uint4
        int v = t + it * 32;                    // 0..511
        int r = v >> 3;                         // k row 0..63
        int c = (v & 7) * 4;
        unsigned dst = (unsigned)__cvta_generic_to_shared(&xs[r][c]);
        const unsigned* src = &g_xd[(kt + r) * B_DIM + bm + c];
        asm volatile("cp.async.cg.shared.global [%0], [%1], 16;\n" :: "r"(dst), "l"(src));
    }
#pragma unroll
    for (int it = 0; it < 4; it++) {            // 64x8 uints = 128 uint4
        int v = t + it * 32;                    // 0..127
        int r = v >> 1;                         // k row 0..63
        int c = (v & 1) * 4;
        unsigned dst = (unsigned)__cvta_generic_to_shared(&ws[r][c]);
        const unsigned* src = &g_wh[(kt + r) * (OUT_F / 2) + bn_h + c];
        asm volatile("cp.async.cg.shared.global [%0], [%1], 16;\n" :: "r"(dst), "l"(src));
    }
    asm volatile("cp.async.commit_group;\n");
}

__global__ __launch_bounds__(32)
void maxmin_main(float* __restrict__ out)
{
    __shared__ unsigned xs[2][BK][BM];        // dup half2, 16 KB
    __shared__ unsigned ws[2][BK][BN / 2];    // packed half2, 4 KB

    const int t    = threadIdx.x;             // 0..31
    const int bn   = blockIdx.x * BN;          // 32 n-blocks
    const int bm   = blockIdx.y * BM;          // 32 m-blocks
    const int bn_h = bn / 2;

    const int tm4 = (t >> 2) * 4;   // m rows tm4..tm4+3   (8 groups)
    const int tn2 = (t & 3) * 2;    // half2 cols tn2,tn2+1 (4 groups -> 4 n)

    issue_stage(t, bm, bn_h, 0, xs[0], ws[0]);
    issue_stage(t, bm, bn_h, BK, xs[1], ws[1]);

    __half2 acc[4][2];              // [m][n-half2]; inputs >= 0: 0 = max-identity
#pragma unroll
    for (int i = 0; i < 4; i++) {
        acc[i][0] = __float2half2_rn(0.f);
        acc[i][1] = __float2half2_rn(0.f);
    }

    for (int i = 0; i < NKT; i++) {
        if (i + 1 < NKT) asm volatile("cp.async.wait_group 1;\n");
        else             asm volatile("cp.async.wait_group 0;\n");
        __syncwarp();

        const int s = i & 1;
#pragma unroll 16
        for (int k = 0; k < BK; k++) {
            uint4 xv = *(const uint4*)&xs[s][k][tm4];            // 4 dup-half2
            __half2 x0 = *(__half2*)&xv.x, x1 = *(__half2*)&xv.y;
            __half2 x2 = *(__half2*)&xv.z, x3 = *(__half2*)&xv.w;
            __half2 w0 = *(const __half2*)&ws[s][k][tn2];
            __half2 w1 = *(const __half2*)&ws[s][k][tn2 + 1];
            acc[0][0] = __hmax2(acc[0][0], __hmin2(x0, w0));
            acc[0][1] = __hmax2(acc[0][1], __hmin2(x0, w1));
            acc[1][0] = __hmax2(acc[1][0], __hmin2(x1, w0));
            acc[1][1] = __hmax2(acc[1][1], __hmin2(x1, w1));
            acc[2][0] = __hmax2(acc[2][0], __hmin2(x2, w0));
            acc[2][1] = __hmax2(acc[2][1], __hmin2(x2, w1));
            acc[3][0] = __hmax2(acc[3][0], __hmin2(x3, w0));
            acc[3][1] = __hmax2(acc[3][1], __hmin2(x3, w1));
        }
        __syncwarp();

        if (i + 2 < NKT)
            issue_stage(t, bm, bn_h, (i + 2) * BK, xs[s], ws[s]);
    }

    // epilogue: fp16 -> fp32, one STG.128 per m row
#pragma unroll
    for (int i = 0; i < 4; i++) {
        float2 a = __half22float2(acc[i][0]);
        float2 b = __half22float2(acc[i][1]);
        *(float4*)(out + (bm + tm4 + i) * OUT_F + bn + tn2 * 2) =
            make_float4(a.x, a.y, b.x, b.y);
    }
}

extern "C" void kernel_launch(void* const* d_in, const int* in_sizes, int n_in,
                              void* d_out, int out_size)
{
    const float* x = (const float*)d_in[0];   // [1024, 512]
    const float* w = (const float*)d_in[1];   // [512, 512]
    float* out = (float*)d_out;               // [1024, 512]

    prep_kernel<<<256, PREP_THREADS>>>(x, w);

    dim3 grid(OUT_F / BN, B_DIM / BM);        // (32, 32) = 1024 CTAs
    maxmin_main<<<grid, 32>>>(out);
}